// round 1
// baseline (speedup 1.0000x reference)
#include <cuda_runtime.h>

#define BATCH 16
#define H 512
#define W 512
#define HW (H * W)
#define PLANE (BATCH * HW)   // 4194304

// ---- scratch (device globals; no allocation allowed) ----
__device__ float g_gray[PLANE];   // gray, later reused as mag
__device__ float g_tmpA[PLANE];   // blur-H intermediate, later dilation row-pass
__device__ float g_blur[PLANE];   // blurred gray
__device__ unsigned char g_dir[PLANE];

// gaussian 5-tap, sigma=1, normalized (f64-accurate constants)
__device__ __forceinline__ float gw(int j) {
    const float G0 = 0.05448868f, G1 = 0.24420134f, G2 = 0.40261996f;
    int a = j < 0 ? -j : j;
    return a == 0 ? G2 : (a == 1 ? G1 : G0);
}

__constant__ int c_dy[8] = {0, 1, 1, 1, 0, -1, -1, -1};
__constant__ int c_dx[8] = {1, 1, 0, -1, -1, -1, 0, 1};

__device__ __forceinline__ int refl(int v, int n) {
    // jnp.pad mode='reflect' (no edge repeat)
    if (v < 0) return -v;
    if (v >= n) return 2 * n - 2 - v;
    return v;
}

// ---------------------------------------------------------------------------
// K1: gray = 0.114*B + 0.587*G + 0.299*R  (input is BGR, unshuffled)
//     x5[b,c] = x[b, perm[b,c]]
__global__ void k_gray_shuffle(const float* __restrict__ x,
                               const int* __restrict__ perm,
                               float* __restrict__ x5) {
    int i = blockIdx.x * blockDim.x + threadIdx.x;
    if (i >= PLANE) return;
    int b = i >> 18;              // / HW
    int p = i & (HW - 1);
    const float* xb = x + (size_t)b * 3 * HW;
    float v0 = xb[p], v1 = xb[HW + p], v2 = xb[2 * HW + p];
    g_gray[i] = 0.114f * v0 + 0.587f * v1 + 0.299f * v2;
    float* ob = x5 + (size_t)b * 3 * HW;
    int p0 = perm[b * 3 + 0], p1 = perm[b * 3 + 1], p2 = perm[b * 3 + 2];
    ob[p]          = p0 == 0 ? v0 : (p0 == 1 ? v1 : v2);
    ob[HW + p]     = p1 == 0 ? v0 : (p1 == 1 ? v1 : v2);
    ob[2 * HW + p] = p2 == 0 ? v0 : (p2 == 1 ? v1 : v2);
}

// ---------------------------------------------------------------------------
// K2: horizontal 5-tap gaussian, reflect border
__global__ void k_blurH() {
    int i = blockIdx.x * blockDim.x + threadIdx.x;
    if (i >= PLANE) return;
    int xc = i & (W - 1);
    int base = i - xc;
    float s = 0.f;
#pragma unroll
    for (int j = -2; j <= 2; ++j)
        s += gw(j) * g_gray[base + refl(xc + j, W)];
    g_tmpA[i] = s;
}

// K3: vertical 5-tap gaussian, reflect border
__global__ void k_blurV() {
    int i = blockIdx.x * blockDim.x + threadIdx.x;
    if (i >= PLANE) return;
    int p = i & (HW - 1);
    int ib = i - p;
    int y = p >> 9, xc = p & (W - 1);
    float s = 0.f;
#pragma unroll
    for (int j = -2; j <= 2; ++j)
        s += gw(j) * g_tmpA[ib + refl(y + j, H) * W + xc];
    g_blur[i] = s;
}

// ---------------------------------------------------------------------------
// K4: sobel (replicate border) -> magnitude + direction index (writes g_gray as mag)
__global__ void k_sobel() {
    int i = blockIdx.x * blockDim.x + threadIdx.x;
    if (i >= PLANE) return;
    int p = i & (HW - 1);
    int ib = i - p;
    int y = p >> 9, x = p & (W - 1);
    int ym = max(y - 1, 0) * W, yc = y * W, yp = min(y + 1, H - 1) * W;
    int xm = max(x - 1, 0), xp = min(x + 1, W - 1);
    const float* im = g_blur + ib;
    float a = im[ym + xm], b2 = im[ym + x], c = im[ym + xp];
    float d = im[yc + xm],                  f = im[yc + xp];
    float g = im[yp + xm], h = im[yp + x],  q = im[yp + xp];
    float gx = (c - a) + 2.f * (f - d) + (q - g);
    float gy = (g - a) + 2.f * (h - b2) + (q - c);
    float m = sqrtf(gx * gx + gy * gy + 1e-6f);
    float ang = atan2f(gy, gx) * 57.29577951308232f;  // degrees
    int k = (int)rintf(ang / 45.0f);                   // round-half-even, like jnp.round
    k = (k + 8) & 7;
    g_gray[i] = m;          // reuse gray buffer as magnitude
    g_dir[i] = (unsigned char)k;
}

// ---------------------------------------------------------------------------
// K5: non-max suppression (zero-padded neighbors, strict >)
__global__ void k_nms(float* __restrict__ out) {
    int i = blockIdx.x * blockDim.x + threadIdx.x;
    if (i >= PLANE) return;
    int p = i & (HW - 1);
    int ib = i - p;
    int y = p >> 9, x = p & (W - 1);
    float m = g_gray[i];
    int k = g_dir[i];
    int dy = c_dy[k], dx = c_dx[k];
    float n1 = 0.f, n2 = 0.f;
    int y1 = y + dy, x1 = x + dx;
    if ((unsigned)y1 < H && (unsigned)x1 < W) n1 = g_gray[ib + y1 * W + x1];
    int y2 = y - dy, x2 = x - dx;
    if ((unsigned)y2 < H && (unsigned)x2 < W) n2 = g_gray[ib + y2 * W + x2];
    out[i] = (m > n1 && m > n2) ? m : 0.f;
}

// ---------------------------------------------------------------------------
// K6/K7: separable dilation (max filter), SAME with XLA padding lo=(k-1)/2
__global__ void k_dilH(const float* __restrict__ src, const int* __restrict__ dptr,
                       int dfallback) {
    int i = blockIdx.x * blockDim.x + threadIdx.x;
    if (i >= PLANE) return;
    int k = dptr ? *dptr : dfallback;
    int lo = (k - 1) >> 1, hi = k - 1 - lo;
    int xc = i & (W - 1);
    int base = i - xc;
    int x0 = max(xc - lo, 0), x1 = min(xc + hi, W - 1);
    float m = src[base + x0];
    for (int x = x0 + 1; x <= x1; ++x) m = fmaxf(m, src[base + x]);
    g_tmpA[i] = m;
}

__global__ void k_dilV(float* __restrict__ dst, const int* __restrict__ dptr,
                       int dfallback) {
    int i = blockIdx.x * blockDim.x + threadIdx.x;
    if (i >= PLANE) return;
    int k = dptr ? *dptr : dfallback;
    int lo = (k - 1) >> 1, hi = k - 1 - lo;
    int p = i & (HW - 1);
    int ib = i - p;
    int y = p >> 9, xc = p & (W - 1);
    int y0 = max(y - lo, 0), y1 = min(y + hi, H - 1);
    float m = g_tmpA[ib + y0 * W + xc];
    for (int yy = y0 + 1; yy <= y1; ++yy) m = fmaxf(m, g_tmpA[ib + yy * W + xc]);
    dst[i] = m;
}

// ---------------------------------------------------------------------------
extern "C" void kernel_launch(void* const* d_in, const int* in_sizes, int n_in,
                              void* d_out, int out_size) {
    const float* x = (const float*)d_in[0];
    const int* perm = (const int*)d_in[1];
    const int* dptr[4] = {nullptr, nullptr, nullptr, nullptr};
    const int dfb[4] = {3, 5, 7, 9};
    for (int i = 0; i < 4; ++i)
        if (n_in >= 3 + i) dptr[i] = (const int*)d_in[2 + i];

    float* out = (float*)d_out;
    float* out_mag = out;                         // [16,1,512,512]
    float* x5 = out + (size_t)5 * PLANE;          // [16,3,512,512]

    const int TB = 256;
    const int GR = PLANE / TB;   // 16384

    k_gray_shuffle<<<GR, TB>>>(x, perm, x5);
    k_blurH<<<GR, TB>>>();
    k_blurV<<<GR, TB>>>();
    k_sobel<<<GR, TB>>>();
    k_nms<<<GR, TB>>>(out_mag);
    for (int i = 0; i < 4; ++i) {
        k_dilH<<<GR, TB>>>(out_mag, dptr[i], dfb[i]);
        k_dilV<<<GR, TB>>>(out + (size_t)(1 + i) * PLANE, dptr[i], dfb[i]);
    }
}

// round 3
// speedup vs baseline: 1.3798x; 1.3798x over previous
#include <cuda_runtime.h>

#define BATCH 16
#define H 512
#define W 512
#define HW (H * W)
#define PLANE (BATCH * HW)   // 4194304

__device__ float g_gray[PLANE];

__device__ __forceinline__ int refl(int v, int n) {
    return v < 0 ? -v : (v >= n ? 2 * n - 2 - v : v);
}

__constant__ signed char c_dy[8] = {0, 1, 1, 1, 0, -1, -1, -1};
__constant__ signed char c_dx[8] = {1, 1, 0, -1, -1, -1, 0, 1};

// ---------------------------------------------------------------------------
// K1: gray = 0.114*B + 0.587*G + 0.299*R (input BGR, unshuffled); x5 = shuffle
// float4 vectorized: 4 pixels / thread.
__global__ void k_gray_shuffle(const float4* __restrict__ x,
                               const int* __restrict__ perm,
                               float4* __restrict__ x5) {
    int i = blockIdx.x * blockDim.x + threadIdx.x;
    if (i >= PLANE / 4) return;
    int b = i >> 16;                  // / (HW/4)
    int p = i & ((HW / 4) - 1);
    const float4* xb = x + (size_t)b * 3 * (HW / 4);
    float4 v0 = xb[p], v1 = xb[(HW / 4) + p], v2 = xb[2 * (HW / 4) + p];
    float4 g;
    g.x = 0.114f * v0.x + 0.587f * v1.x + 0.299f * v2.x;
    g.y = 0.114f * v0.y + 0.587f * v1.y + 0.299f * v2.y;
    g.z = 0.114f * v0.z + 0.587f * v1.z + 0.299f * v2.z;
    g.w = 0.114f * v0.w + 0.587f * v1.w + 0.299f * v2.w;
    ((float4*)g_gray)[i] = g;
    float4* ob = x5 + (size_t)b * 3 * (HW / 4);
    int p0 = perm[b * 3 + 0], p1 = perm[b * 3 + 1], p2 = perm[b * 3 + 2];
    ob[p]                = p0 == 0 ? v0 : (p0 == 1 ? v1 : v2);
    ob[(HW / 4) + p]     = p1 == 0 ? v0 : (p1 == 1 ? v1 : v2);
    ob[2 * (HW / 4) + p] = p2 == 0 ? v0 : (p2 == 1 ? v1 : v2);
}

// ---------------------------------------------------------------------------
// K2: fused blurH + blurV + sobel + mag/dir + NMS over a 32x32 tile (halo 4)
__global__ __launch_bounds__(256) void k_canny(float* __restrict__ out_mag) {
    __shared__ float G[40][41];    // gray tile (reflect-indexed)
    __shared__ float BH[40][37];   // horizontal blur
    __shared__ float B[36][37];    // full blur
    __shared__ float M[34][35];    // magnitude (0 outside image)
    __shared__ unsigned char D[34][35];

    int b = blockIdx.z;
    int y0 = blockIdx.y * 32, x0 = blockIdx.x * 32;
    int tid = threadIdx.y * 32 + threadIdx.x;
    const float* gr = g_gray + (size_t)b * HW;

    // load gray with reflect border (valid for offsets in [-4, H+3])
    for (int idx = tid; idx < 1600; idx += 256) {
        int i = idx / 40, j = idx - 40 * i;
        G[i][j] = gr[refl(y0 - 4 + i, H) * W + refl(x0 - 4 + j, W)];
    }
    __syncthreads();

    const float G0 = 0.05448868f, G1 = 0.24420134f, G2 = 0.40261996f;
    // horizontal blur: BH[i][u] = blur_x at global (y0-4+i, x0-2+u)
    for (int idx = tid; idx < 1440; idx += 256) {
        int i = idx / 36, u = idx - 36 * i;
        BH[i][u] = G0 * (G[i][u] + G[i][u + 4]) + G1 * (G[i][u + 1] + G[i][u + 3])
                 + G2 * G[i][u + 2];
    }
    __syncthreads();
    // vertical blur: B[v][u] = blur at global (y0-2+v, x0-2+u)
    for (int idx = tid; idx < 1296; idx += 256) {
        int v = idx / 36, u = idx - 36 * v;
        B[v][u] = G0 * (BH[v][u] + BH[v + 4][u]) + G1 * (BH[v + 1][u] + BH[v + 3][u])
                + G2 * BH[v + 2][u];
    }
    __syncthreads();

    // sobel (replicate border) + magnitude + direction at global (y0-1+s, x0-1+t)
    for (int idx = tid; idx < 1156; idx += 256) {
        int s = idx / 34, t = idx - 34 * s;
        int gy = y0 - 1 + s, gx = x0 - 1 + t;
        float mval = 0.f;
        unsigned char dir = 0;
        if ((unsigned)gy < H && (unsigned)gx < W) {
            int v = s + 1, u = t + 1;               // B index of center
            int vm = v - (gy > 0), vp = v + (gy < H - 1);
            int um = u - (gx > 0), up = u + (gx < W - 1);
            float a = B[vm][um], b2 = B[vm][u], c = B[vm][up];
            float d = B[v][um],                  f = B[v][up];
            float g = B[vp][um], h = B[vp][u], q = B[vp][up];
            float gxv = (c - a) + 2.f * (f - d) + (q - g);
            float gyv = (g - a) + 2.f * (h - b2) + (q - c);
            mval = sqrtf(gxv * gxv + gyv * gyv + 1e-6f);
            // octant = round(deg(atan2)/45) mod 8, boundaries -> even (half-even)
            const float T = 0.41421356237309503f;   // tan(22.5 deg)
            float ax = fabsf(gxv), ay = fabsf(gyv);
            if (ay <= T * ax)      dir = gxv >= 0.f ? 0 : 4;
            else if (ax <= T * ay) dir = gyv >= 0.f ? 2 : 6;
            else if (gyv >= 0.f)   dir = gxv > 0.f ? 1 : 3;
            else                   dir = gxv > 0.f ? 7 : 5;
        }
        M[s][t] = mval;
        D[s][t] = dir;
    }
    __syncthreads();

    // NMS (zero-pad neighbors handled by M=0 outside image)
    float* ob = out_mag + (size_t)b * HW;
#pragma unroll
    for (int r = 0; r < 4; ++r) {
        int oy = threadIdx.y + 8 * r, ox = threadIdx.x;
        int s = oy + 1, t = ox + 1;
        float m = M[s][t];
        int k = D[s][t];
        int dy = c_dy[k], dx = c_dx[k];
        float n1 = M[s + dy][t + dx];
        float n2 = M[s - dy][t - dx];
        ob[(y0 + oy) * W + x0 + ox] = (m > n1 && m > n2) ? m : 0.f;
    }
}

// ---------------------------------------------------------------------------
// K3: all 4 dilations (3,5,7,9) from one 40x40 tile via max cascade
__global__ __launch_bounds__(256) void k_dilate(const float* __restrict__ src,
                                                float* __restrict__ out) {
    __shared__ float IN[40][41];
    __shared__ float R3[40][41];
    __shared__ float R5[40][41];
    __shared__ float R7[40][41];
    __shared__ float R9[40][41];

    int b = blockIdx.z;
    int y0 = blockIdx.y * 32, x0 = blockIdx.x * 32;
    int tid = threadIdx.x;
    const float* sb = src + (size_t)b * HW;

    for (int idx = tid; idx < 1600; idx += 256) {
        int i = idx / 40, j = idx - 40 * i;
        int gy = y0 - 4 + i, gx = x0 - 4 + j;
        IN[i][j] = ((unsigned)gy < H && (unsigned)gx < W) ? sb[gy * W + gx] : 0.f;
    }
    __syncthreads();
    // row-direction max cascades
    for (int idx = tid; idx < 40 * 38; idx += 256) {
        int i = idx / 38, u = 1 + idx - 38 * i;
        R3[i][u] = fmaxf(fmaxf(IN[i][u - 1], IN[i][u]), IN[i][u + 1]);
    }
    __syncthreads();
    for (int idx = tid; idx < 40 * 36; idx += 256) {
        int i = idx / 36, u = 2 + idx - 36 * i;
        R5[i][u] = fmaxf(R3[i][u - 1], R3[i][u + 1]);
    }
    __syncthreads();
    for (int idx = tid; idx < 40 * 34; idx += 256) {
        int i = idx / 34, u = 3 + idx - 34 * i;
        R7[i][u] = fmaxf(R5[i][u - 1], R5[i][u + 1]);
    }
    __syncthreads();
    for (int idx = tid; idx < 40 * 32; idx += 256) {
        int i = idx / 32, u = 4 + idx - 32 * i;
        R9[i][u] = fmaxf(R7[i][u - 1], R7[i][u + 1]);
    }
    __syncthreads();

    // column-direction max + store all four maps
    for (int idx = tid; idx < 1024; idx += 256) {
        int oy = idx >> 5, ox = idx & 31;
        int i = oy + 4, u = ox + 4;
        float m3 = fmaxf(fmaxf(R3[i - 1][u], R3[i][u]), R3[i + 1][u]);
        float m5 = fmaxf(fmaxf(fmaxf(R5[i - 2][u], R5[i - 1][u]), fmaxf(R5[i][u], R5[i + 1][u])), R5[i + 2][u]);
        float m7 = R7[i - 3][u];
#pragma unroll
        for (int d = -2; d <= 3; ++d) m7 = fmaxf(m7, R7[i + d][u]);
        float m9 = R9[i - 4][u];
#pragma unroll
        for (int d = -3; d <= 4; ++d) m9 = fmaxf(m9, R9[i + d][u]);
        size_t off = (size_t)b * HW + (size_t)(y0 + oy) * W + (x0 + ox);
        out[off] = m3;
        out[PLANE + off] = m5;
        out[2 * (size_t)PLANE + off] = m7;
        out[3 * (size_t)PLANE + off] = m9;
    }
}

// ---------------------------------------------------------------------------
extern "C" void kernel_launch(void* const* d_in, const int* in_sizes, int n_in,
                              void* d_out, int out_size) {
    const float* x = (const float*)d_in[0];
    const int* perm = (const int*)d_in[1];

    float* out = (float*)d_out;
    float* out_mag = out;                       // [16,1,512,512]
    float* out_dil = out + (size_t)PLANE;       // 4 x [16,1,512,512]
    float* x5 = out + (size_t)5 * PLANE;        // [16,3,512,512]

    k_gray_shuffle<<<PLANE / 4 / 256, 256>>>((const float4*)x, perm, (float4*)x5);

    dim3 grid(16, 16, 16);
    dim3 blk(32, 8);
    k_canny<<<grid, blk>>>(out_mag);
    k_dilate<<<grid, 256>>>(out_mag, out_dil);
}